// round 3
// baseline (speedup 1.0000x reference)
#include <cuda_runtime.h>
#include <math.h>

// Problem constants
#define Bq    8
#define Tq    1500
#define Hq    1280
#define Dq    1279          // hidden dim fed to CIF (last channel is alpha logit)
#define Mq    375           // max tokens
#define OUTq  4096
#define MPAD  3072          // 3000 rows padded to multiple of 128
#define ROWS  (Bq*Mq)       // 3000

// ---------------- scratch (device globals: allocation-free) ----------------
__device__ float g_alphas[Bq*Tq];          // scaled alphas
__device__ int   g_pair_t[Bq*2*Tq];        // per-batch flat (t) list
__device__ float g_pair_w[Bq*2*Tq];        // per-batch flat (w) list
__device__ int   g_off[Bq*(Mq+1)];         // CSR offsets per token
__device__ float g_hid[MPAD*Hq];           // CIF output, padded (col 1279 = 0, rows 3000.. = 0)
__device__ float g_t1 [MPAD*Hq];           // after cif_proj
__device__ float g_h2 [MPAD*Hq];           // after rmsnorm
__device__ float g_cifw[Hq*Hq];            // cif_w padded with zero row 1279

// ---------------- K0: sigmoid, pred_num_tokens, scaled alphas ----------------
__global__ void __launch_bounds__(512) alpha_kernel(
    const float* __restrict__ af, const int* __restrict__ nt,
    float* __restrict__ out, int pred_off)
{
    int b = blockIdx.x, tid = threadIdx.x;
    float sg[3];
    float sum = 0.f;
#pragma unroll
    for (int i = 0; i < 3; i++) {
        int t = tid + i*512;
        if (t < Tq) {
            float x = af[((size_t)b*Tq + t)*Hq + (Hq-1)];
            float s = 1.f / (1.f + expf(-x));
            sg[i] = s;
            sum += s;
        } else sg[i] = 0.f;
    }
    __shared__ float red[16];
    __shared__ float s_scale;
#pragma unroll
    for (int o = 16; o; o >>= 1) sum += __shfl_xor_sync(0xffffffffu, sum, o);
    if ((tid & 31) == 0) red[tid >> 5] = sum;
    __syncthreads();
    if (tid == 0) {
        float tot = 0.f;
#pragma unroll
        for (int i = 0; i < 16; i++) tot += red[i];
        out[pred_off + b] = tot;                       // pred_num_tokens
        s_scale = (float)nt[b] / tot;
    }
    __syncthreads();
    float sc = s_scale;
#pragma unroll
    for (int i = 0; i < 3; i++) {
        int t = tid + i*512;
        if (t < Tq) g_alphas[b*Tq + t] = sg[i] * sc;
    }
}

// ---------------- K1: serial CIF scan (1 thread per batch) ----------------
// With scaled alphas < 1 the reference's gated inner loop fires at most once
// per step: either (m, alpha) or a split (m, 1-integrate_pre) + (m', rem).
// Emission order is monotone in m, so each token's pairs are contiguous.
__global__ void __launch_bounds__(256) cif_scan_kernel(const int* __restrict__ nt)
{
    __shared__ float sal[Bq*Tq];   // 48 KB stage of alphas
    int tid = threadIdx.x;
    for (int i = tid; i < Bq*Tq; i += 256) sal[i] = g_alphas[i];
    __syncthreads();
    if (tid >= Bq) return;
    int b = tid;
    const float* al = sal + b*Tq;
    int*   pt  = g_pair_t + b*2*Tq;
    float* pw  = g_pair_w + b*2*Tq;
    int*   off = g_off    + b*(Mq+1);
    int nm1 = nt[b] - 1;
    float integrate = 0.f;
    int m = 0, cnt = 0;
    off[0] = 0;
    for (int t = 0; t < Tq; t++) {
        float alpha = al[t];
        float need  = 1.f - integrate;
        integrate  += alpha;
        if (integrate >= 1.f) {
            pt[cnt] = t; pw[cnt] = need; cnt++;        // a_int into old token
            float rem = alpha - need;
            integrate -= 1.f;
            if (m < nm1) { off[m+1] = cnt; m++; }      // advance (clamped)
            if (t < Tq-1) { pt[cnt] = t; pw[cnt] = rem; cnt++; }   // remainder
        } else {
            pt[cnt] = t; pw[cnt] = alpha; cnt++;
        }
    }
    for (int mm = m+1; mm <= Mq; mm++) off[mm] = cnt;
}

// ---------------- K2: gather  hid[b,m,:] = sum_p w_p * hidden[b,t_p,:] ------
__global__ void __launch_bounds__(256) gather_kernel(const float* __restrict__ af)
{
    int r = blockIdx.x;                 // 0..2999
    int b = r / Mq, m = r % Mq;
    int tid = threadIdx.x;
    int s = g_off[b*(Mq+1) + m];
    int e = g_off[b*(Mq+1) + m + 1];
    float acc[5] = {0.f, 0.f, 0.f, 0.f, 0.f};
    for (int p = s; p < e; p++) {
        int   t = g_pair_t[b*2*Tq + p];
        float w = g_pair_w[b*2*Tq + p];
        const float* row = af + ((size_t)b*Tq + t)*Hq;
#pragma unroll
        for (int i = 0; i < 5; i++) {
            int d = tid + i*256;
            if (d < Dq) acc[i] = fmaf(w, row[d], acc[i]);
        }
    }
    float* o = g_hid + (size_t)r*Hq;
#pragma unroll
    for (int i = 0; i < 5; i++) {
        int d = tid + i*256;
        o[d] = (d < Dq) ? acc[i] : 0.f;     // zero-pad col 1279
    }
}

// ---------------- K3: pad cif_w to [1280,1280] (zero last K row) -----------
__global__ void pad_cifw_kernel(const float* __restrict__ w)
{
    int i = blockIdx.x*256 + threadIdx.x;
    if (i < Hq*Hq) g_cifw[i] = (i < Dq*Hq) ? w[i] : 0.f;
}

// ---------------- sgemm: C[M,N] = A[M,K]*B[K,N] + bias ---------------------
// 128x128 tile, BK=8, 256 threads, 8x8 per thread. M (grid) is MPAD so no
// load guards; only the final store is bounded by Mstore.
__global__ void __launch_bounds__(256) sgemm_kernel(
    const float* __restrict__ A, const float* __restrict__ Bm,
    const float* __restrict__ bias, float* __restrict__ C,
    int N, int K, int Mstore)
{
    __shared__ float As[8][128];
    __shared__ float Bs[8][128];
    const int tid = threadIdx.x;
    const int tx = tid & 15, ty = tid >> 4;
    const float* Ab = A  + (size_t)blockIdx.y*128*K;
    const float* Bb = Bm + (size_t)blockIdx.x*128;
    const int a_row = tid >> 1, a_col = (tid & 1)*4;
    const int b_row = tid >> 5, b_col = (tid & 31)*4;
    float acc[8][8] = {};
    for (int k0 = 0; k0 < K; k0 += 8) {
        float4 av = *(const float4*)(Ab + (size_t)a_row*K + k0 + a_col);
        float4 bv = *(const float4*)(Bb + (size_t)(k0 + b_row)*N + b_col);
        __syncthreads();
        As[a_col+0][a_row] = av.x;
        As[a_col+1][a_row] = av.y;
        As[a_col+2][a_row] = av.z;
        As[a_col+3][a_row] = av.w;
        *(float4*)&Bs[b_row][b_col] = bv;
        __syncthreads();
#pragma unroll
        for (int k = 0; k < 8; k++) {
            float a0[8], b0[8];
            *(float4*)(a0)   = *(const float4*)&As[k][ty*8];
            *(float4*)(a0+4) = *(const float4*)&As[k][ty*8+4];
            *(float4*)(b0)   = *(const float4*)&Bs[k][tx*8];
            *(float4*)(b0+4) = *(const float4*)&Bs[k][tx*8+4];
#pragma unroll
            for (int i = 0; i < 8; i++)
#pragma unroll
                for (int j = 0; j < 8; j++)
                    acc[i][j] = fmaf(a0[i], b0[j], acc[i][j]);
        }
    }
    int row0 = blockIdx.y*128 + ty*8;
    int col0 = blockIdx.x*128 + tx*8;
#pragma unroll
    for (int i = 0; i < 8; i++) {
        int r = row0 + i;
        if (r < Mstore) {
#pragma unroll
            for (int j = 0; j < 8; j += 4) {
                float4 v;
                v.x = acc[i][j+0] + bias[col0+j+0];
                v.y = acc[i][j+1] + bias[col0+j+1];
                v.z = acc[i][j+2] + bias[col0+j+2];
                v.w = acc[i][j+3] + bias[col0+j+3];
                *(float4*)(C + (size_t)r*N + col0 + j) = v;
            }
        }
    }
}

// ---------------- K5: RMSNorm rows of g_t1 -> g_h2 -------------------------
__global__ void __launch_bounds__(256) rmsnorm_kernel(const float* __restrict__ w)
{
    int r = blockIdx.x, tid = threadIdx.x;
    const float* x = g_t1 + (size_t)r*Hq;
    float v[5];
    float ss = 0.f;
#pragma unroll
    for (int i = 0; i < 5; i++) {
        v[i] = x[tid + i*256];
        ss = fmaf(v[i], v[i], ss);
    }
    __shared__ float red[8];
    __shared__ float s_inv;
#pragma unroll
    for (int o = 16; o; o >>= 1) ss += __shfl_xor_sync(0xffffffffu, ss, o);
    if ((tid & 31) == 0) red[tid >> 5] = ss;
    __syncthreads();
    if (tid == 0) {
        float tot = 0.f;
#pragma unroll
        for (int i = 0; i < 8; i++) tot += red[i];
        float rms = sqrtf(tot / (float)Hq + 1e-6f);
        s_inv = 1.f / rms;
    }
    __syncthreads();
    float inv = s_inv;
    float* y = g_h2 + (size_t)r*Hq;
#pragma unroll
    for (int i = 0; i < 5; i++) {
        int d = tid + i*256;
        y[d] = v[i] * inv * w[d];
    }
}

// ---------------- launch ----------------------------------------------------
extern "C" void kernel_launch(void* const* d_in, const int* in_sizes, int n_in,
                              void* d_out, int out_size)
{
    const float* af     = (const float*)d_in[0];   // [8,1500,1280]
    const int*   nt     = (const int*)  d_in[1];   // [8]
    const float* rms_w  = (const float*)d_in[2];   // [1280]
    const float* cif_w  = (const float*)d_in[3];   // [1279,1280]
    const float* cif_b  = (const float*)d_in[4];   // [1280]
    const float* text_w = (const float*)d_in[5];   // [1280,4096]
    const float* text_b = (const float*)d_in[6];   // [4096]
    float* out = (float*)d_out;                    // [8,375,4096] then [8] preds
    int pred_off = out_size - Bq;

    float *p_hid, *p_t1, *p_h2, *p_cifw;
    cudaGetSymbolAddress((void**)&p_hid,  g_hid);
    cudaGetSymbolAddress((void**)&p_t1,   g_t1);
    cudaGetSymbolAddress((void**)&p_h2,   g_h2);
    cudaGetSymbolAddress((void**)&p_cifw, g_cifw);

    alpha_kernel<<<Bq, 512>>>(af, nt, out, pred_off);
    cif_scan_kernel<<<1, 256>>>(nt);
    gather_kernel<<<ROWS, 256>>>(af);
    pad_cifw_kernel<<<(Hq*Hq + 255)/256, 256>>>(cif_w);
    // cif_proj: [3072,1280] x [1280,1280] + cif_b
    sgemm_kernel<<<dim3(Hq/128, MPAD/128), 256>>>(p_hid, p_cifw, cif_b, p_t1, Hq, Hq, MPAD);
    // RMSNorm
    rmsnorm_kernel<<<MPAD, 256>>>(rms_w);
    // text_proj: [3072,1280] x [1280,4096] + text_b, store only 3000 rows
    sgemm_kernel<<<dim3(OUTq/128, MPAD/128), 256>>>(p_h2, text_w, text_b, out, OUTq, Hq, ROWS);
}

// round 7
// speedup vs baseline: 1.5986x; 1.5986x over previous
#include <cuda_runtime.h>
#include <cuda_bf16.h>
#include <math.h>
#include <stdint.h>

// Problem constants
#define Bq    8
#define Tq    1500
#define Hq    1280
#define Dq    1279
#define Mq    375
#define OUTq  4096
#define MPAD  3072
#define ROWS  (Bq*Mq)       // 3000

// ---------------- scratch (device globals: allocation-free) ----------------
__device__ float g_alphas[Bq*Tq];
__device__ int   g_pair_t[Bq*2*Tq];
__device__ float g_pair_w[Bq*2*Tq];
__device__ int   g_off[Bq*(Mq+1)];

__device__ __align__(128) __nv_bfloat16 g_Ahi [MPAD*Hq];   // CIF out hi
__device__ __align__(128) __nv_bfloat16 g_Alo [MPAD*Hq];   // CIF out lo
__device__ __align__(128) float         g_t1  [MPAD*Hq];   // after cif_proj (fp32)
__device__ __align__(128) __nv_bfloat16 g_H2hi[MPAD*Hq];   // rmsnorm out hi
__device__ __align__(128) __nv_bfloat16 g_H2lo[MPAD*Hq];   // rmsnorm out lo
__device__ __align__(128) __nv_bfloat16 g_W1hi[Hq*Hq];     // cif_w^T  [N=1280][K=1280]
__device__ __align__(128) __nv_bfloat16 g_W1lo[Hq*Hq];
__device__ __align__(128) __nv_bfloat16 g_W2hi[OUTq*Hq];   // text_w^T [N=4096][K=1280]
__device__ __align__(128) __nv_bfloat16 g_W2lo[OUTq*Hq];

// ---------------- helpers ----------------------------------------------------
__device__ __forceinline__ uint32_t smem_u32(const void* p) {
    uint32_t a;
    asm("{ .reg .u64 t; cvta.to.shared.u64 t, %1; cvt.u32.u64 %0, t; }" : "=r"(a) : "l"(p));
    return a;
}
#define CP_ASYNC16(dst_u32, src_ptr) \
    asm volatile("cp.async.cg.shared.global [%0], [%1], 16;" \
        :: "r"(dst_u32), "l"(src_ptr) : "memory")
#define CP_COMMIT() asm volatile("cp.async.commit_group;" ::: "memory")
#define CP_WAIT0()  asm volatile("cp.async.wait_group 0;" ::: "memory")

__device__ __forceinline__ void mma16816(float* c, const uint32_t* a, const uint32_t* b) {
    asm volatile(
        "mma.sync.aligned.m16n8k16.row.col.f32.bf16.bf16.f32 "
        "{%0,%1,%2,%3}, {%4,%5,%6,%7}, {%8,%9}, {%0,%1,%2,%3};"
        : "+f"(c[0]), "+f"(c[1]), "+f"(c[2]), "+f"(c[3])
        : "r"(a[0]), "r"(a[1]), "r"(a[2]), "r"(a[3]), "r"(b[0]), "r"(b[1]));
}

__device__ __forceinline__ void split_bf16(float x, __nv_bfloat16& h, __nv_bfloat16& l) {
    h = __float2bfloat16(x);
    l = __float2bfloat16(x - __bfloat162float(h));
}

// ---------------- K0: sigmoid, pred_num_tokens, scaled alphas ---------------
__global__ void __launch_bounds__(512) alpha_kernel(
    const float* __restrict__ af, const int* __restrict__ nt,
    float* __restrict__ out, int pred_off)
{
    int b = blockIdx.x, tid = threadIdx.x;
    float sg[3];
    float sum = 0.f;
#pragma unroll
    for (int i = 0; i < 3; i++) {
        int t = tid + i*512;
        if (t < Tq) {
            float x = af[((size_t)b*Tq + t)*Hq + (Hq-1)];
            float s = 1.f / (1.f + expf(-x));
            sg[i] = s; sum += s;
        } else sg[i] = 0.f;
    }
    __shared__ float red[16];
    __shared__ float s_scale;
#pragma unroll
    for (int o = 16; o; o >>= 1) sum += __shfl_xor_sync(0xffffffffu, sum, o);
    if ((tid & 31) == 0) red[tid >> 5] = sum;
    __syncthreads();
    if (tid == 0) {
        float tot = 0.f;
#pragma unroll
        for (int i = 0; i < 16; i++) tot += red[i];
        out[pred_off + b] = tot;
        s_scale = (float)nt[b] / tot;
    }
    __syncthreads();
    float sc = s_scale;
#pragma unroll
    for (int i = 0; i < 3; i++) {
        int t = tid + i*512;
        if (t < Tq) g_alphas[b*Tq + t] = sg[i] * sc;
    }
}

// ---------------- K1: serial CIF scan (1 thread per batch) ------------------
__global__ void __launch_bounds__(256) cif_scan_kernel(const int* __restrict__ nt)
{
    __shared__ float sal[Bq*Tq];
    int tid = threadIdx.x;
    for (int i = tid; i < Bq*Tq; i += 256) sal[i] = g_alphas[i];
    __syncthreads();
    if (tid >= Bq) return;
    int b = tid;
    const float* al = sal + b*Tq;
    int*   pt  = g_pair_t + b*2*Tq;
    float* pw  = g_pair_w + b*2*Tq;
    int*   off = g_off    + b*(Mq+1);
    int nm1 = nt[b] - 1;
    float integrate = 0.f;
    int m = 0, cnt = 0;
    off[0] = 0;
    for (int t = 0; t < Tq; t++) {
        float alpha = al[t];
        float need  = 1.f - integrate;
        integrate  += alpha;
        if (integrate >= 1.f) {
            pt[cnt] = t; pw[cnt] = need; cnt++;
            float rem = alpha - need;
            integrate -= 1.f;
            if (m < nm1) { off[m+1] = cnt; m++; }
            if (t < Tq-1) { pt[cnt] = t; pw[cnt] = rem; cnt++; }
        } else {
            pt[cnt] = t; pw[cnt] = alpha; cnt++;
        }
    }
    for (int mm = m+1; mm <= Mq; mm++) off[mm] = cnt;
}

// ---------------- K2: gather -> hi/lo bf16 ----------------------------------
__global__ void __launch_bounds__(256) gather_kernel(const float* __restrict__ af)
{
    int r = blockIdx.x;                 // 0..2999
    int b = r / Mq, m = r % Mq;
    int tid = threadIdx.x;
    int s = g_off[b*(Mq+1) + m];
    int e = g_off[b*(Mq+1) + m + 1];
    float acc[5] = {0.f, 0.f, 0.f, 0.f, 0.f};
    for (int p = s; p < e; p++) {
        int   t = g_pair_t[b*2*Tq + p];
        float w = g_pair_w[b*2*Tq + p];
        const float* row = af + ((size_t)b*Tq + t)*Hq;
#pragma unroll
        for (int i = 0; i < 5; i++) {
            int d = tid + i*256;
            if (d < Dq) acc[i] = fmaf(w, row[d], acc[i]);
        }
    }
#pragma unroll
    for (int i = 0; i < 5; i++) {
        int d = tid + i*256;
        float x = (d < Dq) ? acc[i] : 0.f;
        __nv_bfloat16 h, l; split_bf16(x, h, l);
        g_Ahi[(size_t)r*Hq + d] = h;
        g_Alo[(size_t)r*Hq + d] = l;
    }
}

// ---------------- K3: transpose + split weights -> [N][1280] bf16 -----------
__global__ void convw_kernel(const float* __restrict__ W,
                             __nv_bfloat16* __restrict__ hi,
                             __nv_bfloat16* __restrict__ lo, int K, int N)
{
    __shared__ float t[32][33];
    int n0 = blockIdx.x*32, k0 = blockIdx.y*32;
    int tx = threadIdx.x, ty = threadIdx.y;
#pragma unroll
    for (int j = 0; j < 32; j += 8) {
        int k = k0 + ty + j;
        t[ty+j][tx] = (k < K) ? W[(size_t)k*N + n0 + tx] : 0.f;
    }
    __syncthreads();
#pragma unroll
    for (int j = 0; j < 32; j += 8) {
        int n = n0 + ty + j;
        float x = t[tx][ty+j];
        __nv_bfloat16 h, l; split_bf16(x, h, l);
        hi[(size_t)n*Hq + k0 + tx] = h;
        lo[(size_t)n*Hq + k0 + tx] = l;
    }
}

// ---------------- warp-MMA GEMM: C[M,N] = A * B^T + bias --------------------
// A: [MPAD][1280] hi/lo bf16 row-major; Bt: [N][1280] hi/lo bf16 row-major.
// Block 128x128, 8 warps (warp grid 2Mx4N, warp tile 64x32), BK=16,
// double-buffered cp.async, split-bf16 (3 MMAs per tile pair).
// Shared per stage: 4 tensors x 128 rows x 12 words (16 data bf16 + 8 pad).
#define KSTAGES (Hq/16)     // 80
__global__ void __launch_bounds__(256, 1) gemm_kernel(
    const __nv_bfloat16* __restrict__ Ahi, const __nv_bfloat16* __restrict__ Alo,
    const __nv_bfloat16* __restrict__ Bhi, const __nv_bfloat16* __restrict__ Blo,
    const float* __restrict__ bias, float* __restrict__ C,
    int N, int Mstore)
{
    __shared__ uint32_t sm[2][4][128*12];       // 49152 bytes
    const int tid = threadIdx.x;
    const int lane = tid & 31, w = tid >> 5;
    const int wm = w >> 2, wn = w & 3;          // wm:0-1 (64 rows), wn:0-3 (32 cols)
    const int m0 = blockIdx.y * 128, n0 = blockIdx.x * 128;

    // cp.async assignment: this thread loads row ldrow, 16B-half ldh of each tensor
    const int ldrow = tid >> 1, ldh = tid & 1;
    const __nv_bfloat16* gsrc[4] = {
        Ahi + (size_t)(m0 + ldrow)*Hq + ldh*8,
        Alo + (size_t)(m0 + ldrow)*Hq + ldh*8,
        Bhi + (size_t)(n0 + ldrow)*Hq + ldh*8,
        Blo + (size_t)(n0 + ldrow)*Hq + ldh*8 };
    uint32_t sdst[2][4];
#pragma unroll
    for (int bf = 0; bf < 2; bf++)
#pragma unroll
        for (int i = 0; i < 4; i++)
            sdst[bf][i] = smem_u32(&sm[bf][i][ldrow*12 + ldh*4]);

    float acc[4][4][4];
#pragma unroll
    for (int mt = 0; mt < 4; mt++)
#pragma unroll
        for (int nt = 0; nt < 4; nt++)
#pragma unroll
            for (int i = 0; i < 4; i++) acc[mt][nt][i] = 0.f;

    // prologue: stage 0 -> buf 0
#pragma unroll
    for (int i = 0; i < 4; i++) CP_ASYNC16(sdst[0][i], gsrc[i]);
    CP_COMMIT();

    const int r4 = lane >> 2, c4 = lane & 3;
    for (int s = 0; s < KSTAGES; s++) {
        int buf = s & 1;
        CP_WAIT0();
        __syncthreads();
        if (s + 1 < KSTAGES) {
#pragma unroll
            for (int i = 0; i < 4; i++)
                CP_ASYNC16(sdst[buf^1][i], gsrc[i] + (s+1)*16);
            CP_COMMIT();
        }
        // fragments
        uint32_t ah[4][4], al[4][4], bh[4][2], bl[4][2];
#pragma unroll
        for (int mt = 0; mt < 4; mt++) {
            int r = wm*64 + mt*16 + r4;
            const uint32_t* p1 = &sm[buf][0][r*12 + c4];
            ah[mt][0] = p1[0]; ah[mt][1] = p1[96]; ah[mt][2] = p1[4]; ah[mt][3] = p1[100];
            const uint32_t* p2 = &sm[buf][1][r*12 + c4];
            al[mt][0] = p2[0]; al[mt][1] = p2[96]; al[mt][2] = p2[4]; al[mt][3] = p2[100];
        }
#pragma unroll
        for (int nt = 0; nt < 4; nt++) {
            int n = wn*32 + nt*8 + r4;
            const uint32_t* p3 = &sm[buf][2][n*12 + c4];
            bh[nt][0] = p3[0]; bh[nt][1] = p3[4];
            const uint32_t* p4 = &sm[buf][3][n*12 + c4];
            bl[nt][0] = p4[0]; bl[nt][1] = p4[4];
        }
#pragma unroll
        for (int mt = 0; mt < 4; mt++)
#pragma unroll
            for (int nt = 0; nt < 4; nt++) {
                mma16816(acc[mt][nt], ah[mt], bh[nt]);
                mma16816(acc[mt][nt], ah[mt], bl[nt]);
                mma16816(acc[mt][nt], al[mt], bh[nt]);
            }
    }

    // epilogue: C fragment (row lane/4 (+8), col (lane%4)*2 (+1)) + bias
#pragma unroll
    for (int mt = 0; mt < 4; mt++) {
        int row = m0 + wm*64 + mt*16 + r4;
#pragma unroll
        for (int nt = 0; nt < 4; nt++) {
            int col = n0 + wn*32 + nt*8 + c4*2;
            float bx = bias[col], by = bias[col+1];
            if (row < Mstore) {
                float2 v = make_float2(acc[mt][nt][0] + bx, acc[mt][nt][1] + by);
                *(float2*)(C + (size_t)row*N + col) = v;
            }
            if (row + 8 < Mstore) {
                float2 v = make_float2(acc[mt][nt][2] + bx, acc[mt][nt][3] + by);
                *(float2*)(C + (size_t)(row+8)*N + col) = v;
            }
        }
    }
}

// ---------------- K5: RMSNorm rows of g_t1 -> hi/lo bf16 --------------------
__global__ void __launch_bounds__(256) rmsnorm_kernel(const float* __restrict__ w)
{
    int r = blockIdx.x, tid = threadIdx.x;
    const float* x = g_t1 + (size_t)r*Hq;
    float v[5];
    float ss = 0.f;
#pragma unroll
    for (int i = 0; i < 5; i++) {
        v[i] = x[tid + i*256];
        ss = fmaf(v[i], v[i], ss);
    }
    __shared__ float red[8];
    __shared__ float s_inv;
#pragma unroll
    for (int o = 16; o; o >>= 1) ss += __shfl_xor_sync(0xffffffffu, ss, o);
    if ((tid & 31) == 0) red[tid >> 5] = ss;
    __syncthreads();
    if (tid == 0) {
        float tot = 0.f;
#pragma unroll
        for (int i = 0; i < 8; i++) tot += red[i];
        s_inv = 1.f / sqrtf(tot / (float)Hq + 1e-6f);
    }
    __syncthreads();
    float inv = s_inv;
#pragma unroll
    for (int i = 0; i < 5; i++) {
        int d = tid + i*256;
        float y = v[i] * inv * w[d];
        __nv_bfloat16 h, l; split_bf16(y, h, l);
        g_H2hi[(size_t)r*Hq + d] = h;
        g_H2lo[(size_t)r*Hq + d] = l;
    }
}

// ---------------- launch ----------------------------------------------------
extern "C" void kernel_launch(void* const* d_in, const int* in_sizes, int n_in,
                              void* d_out, int out_size)
{
    const float* af     = (const float*)d_in[0];   // [8,1500,1280]
    const int*   nt     = (const int*)  d_in[1];   // [8]
    const float* rms_w  = (const float*)d_in[2];   // [1280]
    const float* cif_w  = (const float*)d_in[3];   // [1279,1280]
    const float* cif_b  = (const float*)d_in[4];   // [1280]
    const float* text_w = (const float*)d_in[5];   // [1280,4096]
    const float* text_b = (const float*)d_in[6];   // [4096]
    float* out = (float*)d_out;
    int pred_off = out_size - Bq;

    __nv_bfloat16 *pAhi, *pAlo, *pH2hi, *pH2lo, *pW1hi, *pW1lo, *pW2hi, *pW2lo;
    float* pT1;
    cudaGetSymbolAddress((void**)&pAhi,  g_Ahi);
    cudaGetSymbolAddress((void**)&pAlo,  g_Alo);
    cudaGetSymbolAddress((void**)&pT1,   g_t1);
    cudaGetSymbolAddress((void**)&pH2hi, g_H2hi);
    cudaGetSymbolAddress((void**)&pH2lo, g_H2lo);
    cudaGetSymbolAddress((void**)&pW1hi, g_W1hi);
    cudaGetSymbolAddress((void**)&pW1lo, g_W1lo);
    cudaGetSymbolAddress((void**)&pW2hi, g_W2hi);
    cudaGetSymbolAddress((void**)&pW2lo, g_W2lo);

    alpha_kernel<<<Bq, 512>>>(af, nt, out, pred_off);
    cif_scan_kernel<<<1, 256>>>(nt);
    gather_kernel<<<ROWS, 256>>>(af);
    convw_kernel<<<dim3(Hq/32,   Hq/32), dim3(32,8)>>>(cif_w,  pW1hi, pW1lo, Dq, Hq);
    convw_kernel<<<dim3(OUTq/32, Hq/32), dim3(32,8)>>>(text_w, pW2hi, pW2lo, Hq, OUTq);
    // cif_proj: [3072,1280] x [1280,1280]^T + cif_b -> t1 (fp32, all MPAD rows)
    gemm_kernel<<<dim3(Hq/128, MPAD/128), 256>>>(
        pAhi, pAlo, pW1hi, pW1lo, cif_b, pT1, Hq, MPAD);
    rmsnorm_kernel<<<MPAD, 256>>>(rms_w);
    // text_proj: [3072,1280] x [4096,1280]^T + text_b -> out (rows < 3000)
    gemm_kernel<<<dim3(OUTq/128, MPAD/128), 256>>>(
        pH2hi, pH2lo, pW2hi, pW2lo, text_b, out, OUTq, ROWS);
}

// round 10
// speedup vs baseline: 2.0808x; 1.3017x over previous
#include <cuda_runtime.h>
#include <cuda_bf16.h>
#include <math.h>
#include <stdint.h>

// Problem constants
#define Bq    8
#define Tq    1500
#define Hq    1280
#define Dq    1279
#define Mq    375
#define OUTq  4096
#define MPAD  3072
#define ROWS  (Bq*Mq)       // 3000

// GEMM tiling
#define BK        32
#define KSTAGES   (Hq/BK)          // 40
#define SW        20               // smem row stride in words (40 bf16 = 32 data + 8 pad)
#define TEN_WORDS (128*SW)         // words per tensor tile (2560)
#define BUF_WORDS (4*TEN_WORDS)    // words per stage buffer (4 tensors)
#define SMEM_GEMM (2*BUF_WORDS*4)  // bytes (81920)

// ---------------- scratch (device globals: allocation-free) ----------------
__device__ float g_alphas[Bq*Tq];
__device__ int   g_pair_t[Bq*2*Tq];
__device__ float g_pair_w[Bq*2*Tq];
__device__ int   g_off[Bq*(Mq+1)];

__device__ __align__(128) __nv_bfloat16 g_Ahi [MPAD*Hq];
__device__ __align__(128) __nv_bfloat16 g_Alo [MPAD*Hq];
__device__ __align__(128) float         g_t1  [MPAD*Hq];
__device__ __align__(128) __nv_bfloat16 g_H2hi[MPAD*Hq];
__device__ __align__(128) __nv_bfloat16 g_H2lo[MPAD*Hq];
__device__ __align__(128) __nv_bfloat16 g_W1hi[Hq*Hq];
__device__ __align__(128) __nv_bfloat16 g_W1lo[Hq*Hq];
__device__ __align__(128) __nv_bfloat16 g_W2hi[OUTq*Hq];
__device__ __align__(128) __nv_bfloat16 g_W2lo[OUTq*Hq];

// ---------------- helpers ----------------------------------------------------
__device__ __forceinline__ uint32_t smem_u32(const void* p) {
    uint32_t a;
    asm("{ .reg .u64 t; cvta.to.shared.u64 t, %1; cvt.u32.u64 %0, t; }" : "=r"(a) : "l"(p));
    return a;
}
#define CP_ASYNC16(dst_u32, src_ptr) \
    asm volatile("cp.async.cg.shared.global [%0], [%1], 16;" \
        :: "r"(dst_u32), "l"(src_ptr) : "memory")
#define CP_COMMIT() asm volatile("cp.async.commit_group;" ::: "memory")
#define CP_WAIT0()  asm volatile("cp.async.wait_group 0;" ::: "memory")

#define LDSM_X4(r0,r1,r2,r3, addr) \
    asm volatile("ldmatrix.sync.aligned.m8n8.x4.shared.b16 {%0,%1,%2,%3}, [%4];" \
        : "=r"(r0), "=r"(r1), "=r"(r2), "=r"(r3) : "r"(addr))

__device__ __forceinline__ void mma16816(float* c, const uint32_t* a, const uint32_t* b) {
    asm volatile(
        "mma.sync.aligned.m16n8k16.row.col.f32.bf16.bf16.f32 "
        "{%0,%1,%2,%3}, {%4,%5,%6,%7}, {%8,%9}, {%0,%1,%2,%3};"
        : "+f"(c[0]), "+f"(c[1]), "+f"(c[2]), "+f"(c[3])
        : "r"(a[0]), "r"(a[1]), "r"(a[2]), "r"(a[3]), "r"(b[0]), "r"(b[1]));
}

__device__ __forceinline__ void split_bf16(float x, __nv_bfloat16& h, __nv_bfloat16& l) {
    h = __float2bfloat16(x);
    l = __float2bfloat16(x - __bfloat162float(h));
}

// ---------------- K0: sigmoid, pred_num_tokens, scaled alphas ---------------
__global__ void __launch_bounds__(512) alpha_kernel(
    const float* __restrict__ af, const int* __restrict__ nt,
    float* __restrict__ out, int pred_off)
{
    int b = blockIdx.x, tid = threadIdx.x;
    float sg[3];
    float sum = 0.f;
#pragma unroll
    for (int i = 0; i < 3; i++) {
        int t = tid + i*512;
        if (t < Tq) {
            float x = af[((size_t)b*Tq + t)*Hq + (Hq-1)];
            float s = 1.f / (1.f + expf(-x));
            sg[i] = s; sum += s;
        } else sg[i] = 0.f;
    }
    __shared__ float red[16];
    __shared__ float s_scale;
#pragma unroll
    for (int o = 16; o; o >>= 1) sum += __shfl_xor_sync(0xffffffffu, sum, o);
    if ((tid & 31) == 0) red[tid >> 5] = sum;
    __syncthreads();
    if (tid == 0) {
        float tot = 0.f;
#pragma unroll
        for (int i = 0; i < 16; i++) tot += red[i];
        out[pred_off + b] = tot;
        s_scale = (float)nt[b] / tot;
    }
    __syncthreads();
    float sc = s_scale;
#pragma unroll
    for (int i = 0; i < 3; i++) {
        int t = tid + i*512;
        if (t < Tq) g_alphas[b*Tq + t] = sg[i] * sc;
    }
}

// ---------------- K1: serial CIF scan (1 thread per batch) ------------------
__global__ void __launch_bounds__(256) cif_scan_kernel(const int* __restrict__ nt)
{
    __shared__ float sal[Bq*Tq];
    int tid = threadIdx.x;
    for (int i = tid; i < Bq*Tq; i += 256) sal[i] = g_alphas[i];
    __syncthreads();
    if (tid >= Bq) return;
    int b = tid;
    const float* al = sal + b*Tq;
    int*   pt  = g_pair_t + b*2*Tq;
    float* pw  = g_pair_w + b*2*Tq;
    int*   off = g_off    + b*(Mq+1);
    int nm1 = nt[b] - 1;
    float integrate = 0.f;
    int m = 0, cnt = 0;
    off[0] = 0;
    for (int t = 0; t < Tq; t++) {
        float alpha = al[t];
        float need  = 1.f - integrate;
        integrate  += alpha;
        if (integrate >= 1.f) {
            pt[cnt] = t; pw[cnt] = need; cnt++;
            float rem = alpha - need;
            integrate -= 1.f;
            if (m < nm1) { off[m+1] = cnt; m++; }
            if (t < Tq-1) { pt[cnt] = t; pw[cnt] = rem; cnt++; }
        } else {
            pt[cnt] = t; pw[cnt] = alpha; cnt++;
        }
    }
    for (int mm = m+1; mm <= Mq; mm++) off[mm] = cnt;
}

// ---------------- K2: gather -> hi/lo bf16 ----------------------------------
__global__ void __launch_bounds__(256) gather_kernel(const float* __restrict__ af)
{
    int r = blockIdx.x;
    int b = r / Mq, m = r % Mq;
    int tid = threadIdx.x;
    int s = g_off[b*(Mq+1) + m];
    int e = g_off[b*(Mq+1) + m + 1];
    float acc[5] = {0.f, 0.f, 0.f, 0.f, 0.f};
    for (int p = s; p < e; p++) {
        int   t = g_pair_t[b*2*Tq + p];
        float w = g_pair_w[b*2*Tq + p];
        const float* row = af + ((size_t)b*Tq + t)*Hq;
#pragma unroll
        for (int i = 0; i < 5; i++) {
            int d = tid + i*256;
            if (d < Dq) acc[i] = fmaf(w, row[d], acc[i]);
        }
    }
#pragma unroll
    for (int i = 0; i < 5; i++) {
        int d = tid + i*256;
        float x = (d < Dq) ? acc[i] : 0.f;
        __nv_bfloat16 h, l; split_bf16(x, h, l);
        g_Ahi[(size_t)r*Hq + d] = h;
        g_Alo[(size_t)r*Hq + d] = l;
    }
}

// ---------------- K3: transpose + split weights -> [N][1280] bf16 -----------
__global__ void convw_kernel(const float* __restrict__ W,
                             __nv_bfloat16* __restrict__ hi,
                             __nv_bfloat16* __restrict__ lo, int K, int N)
{
    __shared__ float t[32][33];
    int n0 = blockIdx.x*32, k0 = blockIdx.y*32;
    int tx = threadIdx.x, ty = threadIdx.y;
#pragma unroll
    for (int j = 0; j < 32; j += 8) {
        int k = k0 + ty + j;
        t[ty+j][tx] = (k < K) ? W[(size_t)k*N + n0 + tx] : 0.f;
    }
    __syncthreads();
#pragma unroll
    for (int j = 0; j < 32; j += 8) {
        int n = n0 + ty + j;
        float x = t[tx][ty+j];
        __nv_bfloat16 h, l; split_bf16(x, h, l);
        hi[(size_t)n*Hq + k0 + tx] = h;
        lo[(size_t)n*Hq + k0 + tx] = l;
    }
}

// ---------------- warp-MMA GEMM: C[M,N] = A * B^T + bias --------------------
// Block 128x128, 8 warps (2Mx4N, warp tile 64x32), BK=32, double-buffered
// cp.async, ldmatrix.x4 fragment loads, split-bf16 (3 MMAs per tile pair).
__global__ void __launch_bounds__(256, 1) gemm_kernel(
    const __nv_bfloat16* __restrict__ Ahi, const __nv_bfloat16* __restrict__ Alo,
    const __nv_bfloat16* __restrict__ Bhi, const __nv_bfloat16* __restrict__ Blo,
    const float* __restrict__ bias, float* __restrict__ C,
    int N, int Mstore)
{
    extern __shared__ uint32_t sm[];      // [2][4][TEN_WORDS]
    const int tid = threadIdx.x;
    const int lane = tid & 31, w = tid >> 5;
    const int wm = w >> 2, wn = w & 3;    // wm:0-1 (64 rows), wn:0-3 (32 cols)
    const int m0 = blockIdx.y * 128, n0 = blockIdx.x * 128;
    const uint32_t sbase = smem_u32(sm);

    // ---- cp.async: 8 chunks/thread/stage; tensor ten, chunk c = j*256+tid
    // row = c>>2 (0..127), ch = c&3 (16B chunk within 64B of K data)
    const __nv_bfloat16* gten[4] = { Ahi + (size_t)m0*Hq, Alo + (size_t)m0*Hq,
                                     Bhi + (size_t)n0*Hq, Blo + (size_t)n0*Hq };
    const __nv_bfloat16* gsrc[8];
    uint32_t sdst[2][8];
#pragma unroll
    for (int ten = 0; ten < 4; ten++)
#pragma unroll
        for (int j = 0; j < 2; j++) {
            int c = j*256 + tid;
            int row = c >> 2, ch = c & 3;
            gsrc[ten*2+j] = gten[ten] + (size_t)row*Hq + ch*8;
            uint32_t off = (ten*TEN_WORDS + row*SW + ch*4) * 4;
            sdst[0][ten*2+j] = sbase + off;
            sdst[1][ten*2+j] = sbase + BUF_WORDS*4 + off;
        }

    // ---- ldmatrix per-lane addresses
    // A (tiles m16k16): lanes 0-7 rows0-7/k0, 8-15 rows8-15/k0, 16-23 rows0-7/k8, 24-31 rows8-15/k8
    const int a_row = wm*64 + (lane & 15);
    const int a_k8  = (lane >> 4);               // 0/1 -> +8 bf16 (= +16 bytes)
    uint32_t aAddrHi = sbase + (0*TEN_WORDS + a_row*SW)*4 + a_k8*16;
    uint32_t aAddrLo = sbase + (1*TEN_WORDS + a_row*SW)*4 + a_k8*16;
    // B pair (two n8k16 tiles): lanes0-7 n0-7/k0, 8-15 n0-7/k8, 16-23 n8-15/k0, 24-31 n8-15/k8
    const int b_n  = wn*32 + (lane & 7) + ((lane >> 4) & 1)*8;
    const int b_k8 = (lane >> 3) & 1;
    uint32_t bAddrHi = sbase + (2*TEN_WORDS + b_n*SW)*4 + b_k8*16;
    uint32_t bAddrLo = sbase + (3*TEN_WORDS + b_n*SW)*4 + b_k8*16;

    float acc[4][4][4];
#pragma unroll
    for (int mt = 0; mt < 4; mt++)
#pragma unroll
        for (int nt = 0; nt < 4; nt++)
#pragma unroll
            for (int i = 0; i < 4; i++) acc[mt][nt][i] = 0.f;

    // prologue: stage 0 -> buf 0
#pragma unroll
    for (int i = 0; i < 8; i++) CP_ASYNC16(sdst[0][i], gsrc[i]);
    CP_COMMIT();

    for (int s = 0; s < KSTAGES; s++) {
        const int buf = s & 1;
        const uint32_t bofs = buf * (BUF_WORDS*4);
        CP_WAIT0();
        __syncthreads();
        if (s + 1 < KSTAGES) {
#pragma unroll
            for (int i = 0; i < 8; i++)
                CP_ASYNC16(sdst[buf^1][i], gsrc[i] + (size_t)(s+1)*BK);
            CP_COMMIT();
        }
#pragma unroll
        for (int kk = 0; kk < 2; kk++) {
            const uint32_t kofs = bofs + kk*32;    // 16 bf16 = 32 bytes per kstep
            uint32_t ah[4][4], al[4][4], bh[8], bl[8];
#pragma unroll
            for (int mt = 0; mt < 4; mt++) {
                uint32_t adr = aAddrHi + kofs + mt*(16*SW*4);
                LDSM_X4(ah[mt][0], ah[mt][1], ah[mt][2], ah[mt][3], adr);
                uint32_t adr2 = aAddrLo + kofs + mt*(16*SW*4);
                LDSM_X4(al[mt][0], al[mt][1], al[mt][2], al[mt][3], adr2);
            }
#pragma unroll
            for (int np = 0; np < 2; np++) {
                uint32_t adr = bAddrHi + kofs + np*(16*SW*4);
                LDSM_X4(bh[np*4+0], bh[np*4+1], bh[np*4+2], bh[np*4+3], adr);
                uint32_t adr2 = bAddrLo + kofs + np*(16*SW*4);
                LDSM_X4(bl[np*4+0], bl[np*4+1], bl[np*4+2], bl[np*4+3], adr2);
            }
#pragma unroll
            for (int mt = 0; mt < 4; mt++)
#pragma unroll
                for (int nt = 0; nt < 4; nt++) {
                    mma16816(acc[mt][nt], ah[mt], &bh[nt*2]);
                    mma16816(acc[mt][nt], ah[mt], &bl[nt*2]);
                    mma16816(acc[mt][nt], al[mt], &bh[nt*2]);
                }
        }
    }

    // epilogue: row lane/4 (+8), col (lane%4)*2 (+1), add bias
    const int r4 = lane >> 2, c4 = lane & 3;
#pragma unroll
    for (int mt = 0; mt < 4; mt++) {
        int row = m0 + wm*64 + mt*16 + r4;
#pragma unroll
        for (int nt = 0; nt < 4; nt++) {
            int col = n0 + wn*32 + nt*8 + c4*2;
            float bx = bias[col], by = bias[col+1];
            if (row < Mstore) {
                float2 v = make_float2(acc[mt][nt][0] + bx, acc[mt][nt][1] + by);
                *(float2*)(C + (size_t)row*N + col) = v;
            }
            if (row + 8 < Mstore) {
                float2 v = make_float2(acc[mt][nt][2] + bx, acc[mt][nt][3] + by);
                *(float2*)(C + (size_t)(row+8)*N + col) = v;
            }
        }
    }
}

// ---------------- K5: RMSNorm rows of g_t1 -> hi/lo bf16 --------------------
__global__ void __launch_bounds__(256) rmsnorm_kernel(const float* __restrict__ w)
{
    int r = blockIdx.x, tid = threadIdx.x;
    const float* x = g_t1 + (size_t)r*Hq;
    float v[5];
    float ss = 0.f;
#pragma unroll
    for (int i = 0; i < 5; i++) {
        v[i] = x[tid + i*256];
        ss = fmaf(v[i], v[i], ss);
    }
    __shared__ float red[8];
    __shared__ float s_inv;
#pragma unroll
    for (int o = 16; o; o >>= 1) ss += __shfl_xor_sync(0xffffffffu, ss, o);
    if ((tid & 31) == 0) red[tid >> 5] = ss;
    __syncthreads();
    if (tid == 0) {
        float tot = 0.f;
#pragma unroll
        for (int i = 0; i < 8; i++) tot += red[i];
        s_inv = 1.f / sqrtf(tot / (float)Hq + 1e-6f);
    }
    __syncthreads();
    float inv = s_inv;
#pragma unroll
    for (int i = 0; i < 5; i++) {
        int d = tid + i*256;
        float y = v[i] * inv * w[d];
        __nv_bfloat16 h, l; split_bf16(y, h, l);
        g_H2hi[(size_t)r*Hq + d] = h;
        g_H2lo[(size_t)r*Hq + d] = l;
    }
}

// ---------------- launch ----------------------------------------------------
extern "C" void kernel_launch(void* const* d_in, const int* in_sizes, int n_in,
                              void* d_out, int out_size)
{
    const float* af     = (const float*)d_in[0];
    const int*   nt     = (const int*)  d_in[1];
    const float* rms_w  = (const float*)d_in[2];
    const float* cif_w  = (const float*)d_in[3];
    const float* cif_b  = (const float*)d_in[4];
    const float* text_w = (const float*)d_in[5];
    const float* text_b = (const float*)d_in[6];
    float* out = (float*)d_out;
    int pred_off = out_size - Bq;

    __nv_bfloat16 *pAhi, *pAlo, *pH2hi, *pH2lo, *pW1hi, *pW1lo, *pW2hi, *pW2lo;
    float* pT1;
    cudaGetSymbolAddress((void**)&pAhi,  g_Ahi);
    cudaGetSymbolAddress((void**)&pAlo,  g_Alo);
    cudaGetSymbolAddress((void**)&pT1,   g_t1);
    cudaGetSymbolAddress((void**)&pH2hi, g_H2hi);
    cudaGetSymbolAddress((void**)&pH2lo, g_H2lo);
    cudaGetSymbolAddress((void**)&pW1hi, g_W1hi);
    cudaGetSymbolAddress((void**)&pW1lo, g_W1lo);
    cudaGetSymbolAddress((void**)&pW2hi, g_W2hi);
    cudaGetSymbolAddress((void**)&pW2lo, g_W2lo);

    cudaFuncSetAttribute(gemm_kernel,
                         cudaFuncAttributeMaxDynamicSharedMemorySize, SMEM_GEMM);

    alpha_kernel<<<Bq, 512>>>(af, nt, out, pred_off);
    cif_scan_kernel<<<1, 256>>>(nt);
    gather_kernel<<<ROWS, 256>>>(af);
    convw_kernel<<<dim3(Hq/32,   Hq/32), dim3(32,8)>>>(cif_w,  pW1hi, pW1lo, Dq, Hq);
    convw_kernel<<<dim3(OUTq/32, Hq/32), dim3(32,8)>>>(text_w, pW2hi, pW2lo, Hq, OUTq);
    // cif_proj: [3072,1280] x [1280,1280]^T + cif_b -> t1 (fp32, all MPAD rows)
    gemm_kernel<<<dim3(Hq/128, MPAD/128), 256, SMEM_GEMM>>>(
        pAhi, pAlo, pW1hi, pW1lo, cif_b, pT1, Hq, MPAD);
    rmsnorm_kernel<<<MPAD, 256>>>(rms_w);
    // text_proj: [3072,1280] x [4096,1280]^T + text_b -> out (rows < 3000)
    gemm_kernel<<<dim3(OUTq/128, MPAD/128), 256, SMEM_GEMM>>>(
        pH2hi, pH2lo, pW2hi, pW2lo, text_b, out, OUTq, ROWS);
}